// round 12
// baseline (speedup 1.0000x reference)
#include <cuda_runtime.h>

#define N_POINTS    32768
#define EMB         64
#define NUM_CLASSES 50
#define NUM_HOUSES  5
#define NUM_WIN     6            // NUM_WINDOWS + 1 (last = frame)
#define BOXES       (NUM_HOUSES * NUM_WIN)   // 30

// Output: data (N*64) | contains (50*N) | dists (50*30*N)
#define OUT_CONTAINS ((size_t)N_POINTS * EMB)
#define OUT_DISTS    (OUT_CONTAINS + (size_t)NUM_CLASSES * N_POINTS)

typedef unsigned long long u64;

__device__ __forceinline__ u64 f32x2_sub(u64 a, u64 b) {
    u64 r; asm("sub.rn.f32x2 %0, %1, %2;" : "=l"(r) : "l"(a), "l"(b)); return r;
}
__device__ __forceinline__ u64 f32x2_add(u64 a, u64 b) {
    u64 r; asm("add.rn.f32x2 %0, %1, %2;" : "=l"(r) : "l"(a), "l"(b)); return r;
}
__device__ __forceinline__ u64 f32x2_mul(u64 a, u64 b) {
    u64 r; asm("mul.rn.f32x2 %0, %1, %2;" : "=l"(r) : "l"(a), "l"(b)); return r;
}
__device__ __forceinline__ u64 f32x2_fma(u64 a, u64 b, u64 c) {
    u64 r; asm("fma.rn.f32x2 %0, %1, %2, %3;" : "=l"(r) : "l"(a), "l"(b), "l"(c)); return r;
}
__device__ __forceinline__ u64 pack2(float x, float y) {
    u64 r; asm("mov.b64 %0, {%1, %2};" : "=l"(r) : "f"(x), "f"(y)); return r;
}
__device__ __forceinline__ void unpack2(u64 v, float& x, float& y) {
    asm("mov.b64 {%0, %1}, %2;" : "=f"(x), "=f"(y) : "l"(v));
}

// Route A (clamp form), 2 points sharing one box LDS. bb=(lo0,lo1,hi0,hi1).
// per 2 dims per point: 4 FMNMX (alu) + packed sub + packed fma (fma pipe).
#define PAIRA2(J, ACC_A, ACC_B, OP_A, OP_B) {                     \
    const ulonglong2 bb = bx[(J)];                                \
    float lo0, lo1, hi0, hi1;                                     \
    unpack2(bb.x, lo0, lo1); unpack2(bb.y, hi0, hi1);             \
    float ax, ay, qx, qy;                                         \
    unpack2(p0[(J)], ax, ay); unpack2(p1[(J)], qx, qy);           \
    const float ca0 = fminf(fmaxf(ax, lo0), hi0);                 \
    const float ca1 = fminf(fmaxf(ay, lo1), hi1);                 \
    const float cb0 = fminf(fmaxf(qx, lo0), hi0);                 \
    const float cb1 = fminf(fmaxf(qy, lo1), hi1);                 \
    const u64 da = f32x2_sub(p0[(J)], pack2(ca0, ca1));           \
    const u64 db = f32x2_sub(p1[(J)], pack2(cb0, cb1));           \
    ACC_A = OP_A; ACC_B = OP_B; }

#define PAIRA2_FMA(J, A, B) PAIRA2(J, A, B, f32x2_fma(da,da,A), f32x2_fma(db,db,B))
#define PAIRA2_MUL(J, A, B) PAIRA2(J, A, B, f32x2_mul(da,da),   f32x2_mul(db,db))

// Route C (center form), 2 points sharing one box LDS. bb=(ctr0,ctr1,hw0,hw1).
// per 2 dims per point: packed sub + 2 FADD(|t|-hw) + packed fma (fma pipe),
// 2 FMNMX (alu).
#define PAIRC2(J, ACC_A, ACC_B, OP_A, OP_B) {                     \
    const ulonglong2 bb = bx[(J)];                                \
    float h0, h1; unpack2(bb.y, h0, h1);                          \
    const u64 ta = f32x2_sub(p0[(J)], bb.x);                      \
    const u64 tb = f32x2_sub(p1[(J)], bb.x);                      \
    float tax, tay, tbx, tby;                                     \
    unpack2(ta, tax, tay); unpack2(tb, tbx, tby);                 \
    const float da0 = fmaxf(fabsf(tax) - h0, 0.0f);               \
    const float da1 = fmaxf(fabsf(tay) - h1, 0.0f);               \
    const float db0 = fmaxf(fabsf(tbx) - h0, 0.0f);               \
    const float db1 = fmaxf(fabsf(tby) - h1, 0.0f);               \
    const u64 da = pack2(da0, da1);                               \
    const u64 db = pack2(db0, db1);                               \
    ACC_A = OP_A; ACC_B = OP_B; }

#define PAIRC2_FMA(J, A, B) PAIRC2(J, A, B, f32x2_fma(da,da,A), f32x2_fma(db,db,B))
#define PAIRC2_MUL(J, A, B) PAIRC2(J, A, B, f32x2_mul(da,da),   f32x2_mul(db,db))

#define GRP_STRIDE 17  // 16 data float4 + 1 pad -> 272B group skew (4 banks)

__global__ __launch_bounds__(256, 2)
void geom_kernel(const float* __restrict__ data,
                 const float* __restrict__ shape,   // [50][5][6][2][64]
                 float* __restrict__ out)
{
    // s_box[box][g*17 + slot]: slot&7 < 2 -> (lo0,lo1,hi0,hi1)   [route A]
    //                          else       -> (ctr0,ctr1,hw0,hw1)  [route C]
    // 4A:12C mix per 16 pairs balances alu vs fma including overhead.
    // Half-warp broadcast addresses differ by 68 words == 4 banks (mod 32)
    // -> disjoint bank quads, conflict-free LDS.128.
    __shared__ float4 s_box[BOXES][2 * GRP_STRIDE];

    const int c   = blockIdx.y;
    const int tid = threadIdx.x;

    // ---- stage this class's 30 boxes ----
    const float2* sb2 = reinterpret_cast<const float2*>(
        shape + (size_t)c * (BOXES * 2 * EMB));
    #pragma unroll
    for (int e = tid; e < BOXES * 32; e += 256) {
        const int box = e >> 5;
        const int j   = e & 31;                    // pair = dims 2j, 2j+1
        const float2 a = sb2[box * 64 + j];        // corner 0
        const float2 b = sb2[box * 64 + 32 + j];   // corner 1
        const float lo0 = fminf(a.x, b.x), hi0 = fmaxf(a.x, b.x);
        const float lo1 = fminf(a.y, b.y), hi1 = fmaxf(a.y, b.y);
        float4 v;
        if ((j & 7) < 2)   // route A slot
            v = make_float4(lo0, lo1, hi0, hi1);
        else               // route C slot
            v = make_float4(0.5f * (lo0 + hi0), 0.5f * (lo1 + hi1),
                            0.5f * (hi0 - lo0), 0.5f * (hi1 - lo1));
        s_box[box][(j >> 4) * GRP_STRIDE + (j & 15)] = v;
    }

    // ---- data passthrough (class-slice 0 only): linear block copy ----
    if (blockIdx.y == 0) {
        // this block covers 256 points = 16384 floats = 4096 float4
        const float4* src = reinterpret_cast<const float4*>(
            data + (size_t)blockIdx.x * 256 * EMB);
        float4* dst = reinterpret_cast<float4*>(
            out + (size_t)blockIdx.x * 256 * EMB);
        #pragma unroll
        for (int k = 0; k < 16; k++)
            dst[tid + 256 * k] = src[tid + 256 * k];
    }
    __syncthreads();

    // ---- 2 threads per point, 2 points per thread: 32 points/warp ----
    const int lane = tid & 31;
    const int warp = tid >> 5;
    const int g    = lane >> 4;   // dim group: dims [g*32, g*32+32)
    const int i    = lane & 15;
    const int n0   = blockIdx.x * 256 + warp * 32 + i;   // and n0+16

    // 32 dims per point = 16 packed f32x2, two points
    u64 p0[16], p1[16];
    {
        const ulonglong2* dp0 = reinterpret_cast<const ulonglong2*>(
            data + (size_t)n0 * EMB + g * 32);
        const ulonglong2* dp1 = reinterpret_cast<const ulonglong2*>(
            data + (size_t)(n0 + 16) * EMB + g * 32);
        #pragma unroll
        for (int k = 0; k < 8; k++) {
            const ulonglong2 v0 = dp0[k];
            const ulonglong2 v1 = dp1[k];
            p0[2 * k] = v0.x;  p0[2 * k + 1] = v0.y;
            p1[2 * k] = v1.x;  p1[2 * k + 1] = v1.y;
        }
    }

    // dists base for this thread; per-h advance is a single pointer add,
    // per-w offsets are compile-time constants folded into STG immediates.
    float* __restrict__ od = out + OUT_DISTS
                           + (size_t)c * BOXES * N_POINTS + n0;

    bool town0 = false, town1 = false;
    #pragma unroll 1
    for (int h = 0; h < NUM_HOUSES; h++) {
        bool anyw0 = false, frame0 = false;
        bool anyw1 = false, frame1 = false;
        #pragma unroll
        for (int w = 0; w < NUM_WIN; w++) {
            const ulonglong2* bx = reinterpret_cast<const ulonglong2*>(
                &s_box[h * NUM_WIN + w][g * GRP_STRIDE]);
            u64 a0, a1, b0, b1;
            // 4A:12C route mix (A on slots 0,1,8,9)
            PAIRA2_MUL(0, a0, b0)
            PAIRA2_MUL(1, a1, b1)
            PAIRC2_FMA(2, a0, b0)
            PAIRC2_FMA(3, a1, b1)
            PAIRC2_FMA(4, a0, b0)
            PAIRC2_FMA(5, a1, b1)
            PAIRC2_FMA(6, a0, b0)
            PAIRC2_FMA(7, a1, b1)
            PAIRA2_FMA(8, a0, b0)
            PAIRA2_FMA(9, a1, b1)
            PAIRC2_FMA(10, a0, b0)
            PAIRC2_FMA(11, a1, b1)
            PAIRC2_FMA(12, a0, b0)
            PAIRC2_FMA(13, a1, b1)
            PAIRC2_FMA(14, a0, b0)
            PAIRC2_FMA(15, a1, b1)
            const u64 sa = f32x2_add(a0, a1);
            const u64 sb = f32x2_add(b0, b1);
            float x0, y0, x1, y1;
            unpack2(sa, x0, y0);
            unpack2(sb, x1, y1);
            float sq0 = x0 + y0;
            float sq1 = x1 + y1;
            // combine the two 32-dim halves (lanes xor 16); 1 shfl per point
            sq0 += __shfl_xor_sync(0xffffffffu, sq0, 16);
            sq1 += __shfl_xor_sync(0xffffffffu, sq1, 16);

            // inside <=> all per-dim deltas 0 <=> sq == 0 (partials >= 0)
            const bool ins0 = (sq0 == 0.0f);
            const bool ins1 = (sq1 == 0.0f);
            if (w < NUM_WIN - 1) { anyw0 |= ins0; anyw1 |= ins1; }
            else                 { frame0 = ins0; frame1 = ins1; }

            if (g == 0) {
                float d0, d1;
                asm("sqrt.approx.f32 %0, %1;" : "=f"(d0) : "f"(sq0));
                asm("sqrt.approx.f32 %0, %1;" : "=f"(d1) : "f"(sq1));
                od[w * N_POINTS]      = d0;   // constant STG offsets
                od[w * N_POINTS + 16] = d1;
            }
        }
        town0 |= (frame0 && !anyw0);
        town1 |= (frame1 && !anyw1);
        od += NUM_WIN * N_POINTS;
    }

    if (g == 0) {
        out[OUT_CONTAINS + (size_t)c * N_POINTS + n0]      = town0 ? 1.0f : 0.0f;
        out[OUT_CONTAINS + (size_t)c * N_POINTS + n0 + 16] = town1 ? 1.0f : 0.0f;
    }
}

extern "C" void kernel_launch(void* const* d_in, const int* in_sizes, int n_in,
                              void* d_out, int out_size) {
    const float* data  = (const float*)d_in[0];
    const float* shape = (const float*)d_in[1];
    float* out = (float*)d_out;

    dim3 grid(N_POINTS / 256, NUM_CLASSES);
    geom_kernel<<<grid, 256>>>(data, shape, out);
}

// round 13
// speedup vs baseline: 1.5660x; 1.5660x over previous
#include <cuda_runtime.h>

#define N_POINTS    32768
#define EMB         64
#define NUM_CLASSES 50
#define NUM_HOUSES  5
#define NUM_WIN     6            // NUM_WINDOWS + 1 (last = frame)
#define BOXES       (NUM_HOUSES * NUM_WIN)   // 30

// Output: data (N*64) | contains (50*N) | dists (50*30*N)
#define OUT_CONTAINS ((size_t)N_POINTS * EMB)
#define OUT_DISTS    (OUT_CONTAINS + (size_t)NUM_CLASSES * N_POINTS)

typedef unsigned long long u64;

__device__ __forceinline__ u64 f32x2_sub(u64 a, u64 b) {
    u64 r; asm("sub.rn.f32x2 %0, %1, %2;" : "=l"(r) : "l"(a), "l"(b)); return r;
}
__device__ __forceinline__ u64 f32x2_add(u64 a, u64 b) {
    u64 r; asm("add.rn.f32x2 %0, %1, %2;" : "=l"(r) : "l"(a), "l"(b)); return r;
}
__device__ __forceinline__ u64 f32x2_mul(u64 a, u64 b) {
    u64 r; asm("mul.rn.f32x2 %0, %1, %2;" : "=l"(r) : "l"(a), "l"(b)); return r;
}
__device__ __forceinline__ u64 f32x2_fma(u64 a, u64 b, u64 c) {
    u64 r; asm("fma.rn.f32x2 %0, %1, %2, %3;" : "=l"(r) : "l"(a), "l"(b), "l"(c)); return r;
}
__device__ __forceinline__ u64 pack2(float x, float y) {
    u64 r; asm("mov.b64 %0, {%1, %2};" : "=l"(r) : "f"(x), "f"(y)); return r;
}
__device__ __forceinline__ void unpack2(u64 v, float& x, float& y) {
    asm("mov.b64 {%0, %1}, %2;" : "=f"(x), "=f"(y) : "l"(v));
}

// Route A (clamp form), 2 points sharing one box LDS. bb=(lo0,lo1,hi0,hi1).
#define PAIRA2(J, ACC_A, ACC_B, OP_A, OP_B) {                     \
    const ulonglong2 bb = bx[(J)];                                \
    float lo0, lo1, hi0, hi1;                                     \
    unpack2(bb.x, lo0, lo1); unpack2(bb.y, hi0, hi1);             \
    float ax, ay, qx, qy;                                         \
    unpack2(p0[(J)], ax, ay); unpack2(p1[(J)], qx, qy);           \
    const float ca0 = fminf(fmaxf(ax, lo0), hi0);                 \
    const float ca1 = fminf(fmaxf(ay, lo1), hi1);                 \
    const float cb0 = fminf(fmaxf(qx, lo0), hi0);                 \
    const float cb1 = fminf(fmaxf(qy, lo1), hi1);                 \
    const u64 da = f32x2_sub(p0[(J)], pack2(ca0, ca1));           \
    const u64 db = f32x2_sub(p1[(J)], pack2(cb0, cb1));           \
    ACC_A = OP_A; ACC_B = OP_B; }

#define PAIRA2_FMA(J, A, B) PAIRA2(J, A, B, f32x2_fma(da,da,A), f32x2_fma(db,db,B))
#define PAIRA2_MUL(J, A, B) PAIRA2(J, A, B, f32x2_mul(da,da),   f32x2_mul(db,db))

// Route C (center form), 2 points sharing one box LDS. bb=(ctr0,ctr1,hw0,hw1).
#define PAIRC2(J, ACC_A, ACC_B, OP_A, OP_B) {                     \
    const ulonglong2 bb = bx[(J)];                                \
    float h0, h1; unpack2(bb.y, h0, h1);                          \
    const u64 ta = f32x2_sub(p0[(J)], bb.x);                      \
    const u64 tb = f32x2_sub(p1[(J)], bb.x);                      \
    float tax, tay, tbx, tby;                                     \
    unpack2(ta, tax, tay); unpack2(tb, tbx, tby);                 \
    const float da0 = fmaxf(fabsf(tax) - h0, 0.0f);               \
    const float da1 = fmaxf(fabsf(tay) - h1, 0.0f);               \
    const float db0 = fmaxf(fabsf(tbx) - h0, 0.0f);               \
    const float db1 = fmaxf(fabsf(tby) - h1, 0.0f);               \
    const u64 da = pack2(da0, da1);                               \
    const u64 db = pack2(db0, db1);                               \
    ACC_A = OP_A; ACC_B = OP_B; }

#define PAIRC2_FMA(J, A, B) PAIRC2(J, A, B, f32x2_fma(da,da,A), f32x2_fma(db,db,B))
#define PAIRC2_MUL(J, A, B) PAIRC2(J, A, B, f32x2_mul(da,da),   f32x2_mul(db,db))

#define GRP_STRIDE 17  // 16 data float4 + 1 pad -> 272B group skew (4 banks)

__global__ __launch_bounds__(256, 2)
void geom_kernel(const float* __restrict__ data,
                 const float* __restrict__ shape,   // [50][5][6][2][64]
                 float* __restrict__ out)
{
    // s_box[box][g*17 + slot]: slot&7 < 2 -> (lo0,lo1,hi0,hi1)   [route A]
    //                          else       -> (ctr0,ctr1,hw0,hw1)  [route C]
    // 4A:12C mix per 16 pairs balances alu vs fma including overhead.
    // Half-warp broadcast addresses differ by 68 words == 4 banks (mod 32)
    // -> disjoint bank quads, conflict-free LDS.128.
    __shared__ float4 s_box[BOXES][2 * GRP_STRIDE];

    const int c   = blockIdx.y;
    const int tid = threadIdx.x;

    // ---- stage this class's 30 boxes ----
    const float2* sb2 = reinterpret_cast<const float2*>(
        shape + (size_t)c * (BOXES * 2 * EMB));
    #pragma unroll
    for (int e = tid; e < BOXES * 32; e += 256) {
        const int box = e >> 5;
        const int j   = e & 31;                    // pair = dims 2j, 2j+1
        const float2 a = sb2[box * 64 + j];        // corner 0
        const float2 b = sb2[box * 64 + 32 + j];   // corner 1
        const float lo0 = fminf(a.x, b.x), hi0 = fmaxf(a.x, b.x);
        const float lo1 = fminf(a.y, b.y), hi1 = fmaxf(a.y, b.y);
        float4 v;
        if ((j & 7) < 2)   // route A slot
            v = make_float4(lo0, lo1, hi0, hi1);
        else               // route C slot
            v = make_float4(0.5f * (lo0 + hi0), 0.5f * (lo1 + hi1),
                            0.5f * (hi0 - lo0), 0.5f * (hi1 - lo1));
        s_box[box][(j >> 4) * GRP_STRIDE + (j & 15)] = v;
    }

    // ---- data passthrough (class-slice 0 only): linear block copy ----
    if (blockIdx.y == 0) {
        // this block covers 256 points = 16384 floats = 4096 float4
        const float4* src = reinterpret_cast<const float4*>(
            data + (size_t)blockIdx.x * 256 * EMB);
        float4* dst = reinterpret_cast<float4*>(
            out + (size_t)blockIdx.x * 256 * EMB);
        #pragma unroll
        for (int k = 0; k < 16; k++)
            dst[tid + 256 * k] = src[tid + 256 * k];
    }
    __syncthreads();

    // ---- 2 threads per point, 2 points per thread: 32 points/warp ----
    const int lane = tid & 31;
    const int warp = tid >> 5;
    const int g    = lane >> 4;   // dim group: dims [g*32, g*32+32)
    const int i    = lane & 15;
    const int n0   = blockIdx.x * 256 + warp * 32 + i;   // and n0+16

    // 32 dims per point = 16 packed f32x2, two points
    u64 p0[16], p1[16];
    {
        const ulonglong2* dp0 = reinterpret_cast<const ulonglong2*>(
            data + (size_t)n0 * EMB + g * 32);
        const ulonglong2* dp1 = reinterpret_cast<const ulonglong2*>(
            data + (size_t)(n0 + 16) * EMB + g * 32);
        #pragma unroll
        for (int k = 0; k < 8; k++) {
            const ulonglong2 v0 = dp0[k];
            const ulonglong2 v1 = dp1[k];
            p0[2 * k] = v0.x;  p0[2 * k + 1] = v0.y;
            p1[2 * k] = v1.x;  p1[2 * k + 1] = v1.y;
        }
    }

    float* __restrict__ out_dists = out + OUT_DISTS
                                  + (size_t)c * BOXES * N_POINTS + n0;

    bool town0 = false, town1 = false;
    #pragma unroll 1
    for (int h = 0; h < NUM_HOUSES; h++) {
        bool anyw0 = false, frame0 = false;
        bool anyw1 = false, frame1 = false;
        #pragma unroll 2
        for (int w = 0; w < NUM_WIN; w++) {
            const int box = h * NUM_WIN + w;
            const ulonglong2* bx = reinterpret_cast<const ulonglong2*>(
                &s_box[box][g * GRP_STRIDE]);
            u64 a0, a1, b0, b1;
            // 4A:12C route mix (A on slots 0,1,8,9), R11 loop structure
            PAIRA2_MUL(0, a0, b0)
            PAIRA2_MUL(1, a1, b1)
            PAIRC2_FMA(2, a0, b0)
            PAIRC2_FMA(3, a1, b1)
            PAIRC2_FMA(4, a0, b0)
            PAIRC2_FMA(5, a1, b1)
            PAIRC2_FMA(6, a0, b0)
            PAIRC2_FMA(7, a1, b1)
            PAIRA2_FMA(8, a0, b0)
            PAIRA2_FMA(9, a1, b1)
            PAIRC2_FMA(10, a0, b0)
            PAIRC2_FMA(11, a1, b1)
            PAIRC2_FMA(12, a0, b0)
            PAIRC2_FMA(13, a1, b1)
            PAIRC2_FMA(14, a0, b0)
            PAIRC2_FMA(15, a1, b1)
            const u64 sa = f32x2_add(a0, a1);
            const u64 sb = f32x2_add(b0, b1);
            float x0, y0, x1, y1;
            unpack2(sa, x0, y0);
            unpack2(sb, x1, y1);
            float sq0 = x0 + y0;
            float sq1 = x1 + y1;
            // combine the two 32-dim halves (lanes xor 16); 1 shfl per point
            sq0 += __shfl_xor_sync(0xffffffffu, sq0, 16);
            sq1 += __shfl_xor_sync(0xffffffffu, sq1, 16);

            // inside <=> all per-dim deltas 0 <=> sq == 0 (partials >= 0)
            const bool ins0 = (sq0 == 0.0f);
            const bool ins1 = (sq1 == 0.0f);
            if (w < NUM_WIN - 1) { anyw0 |= ins0; anyw1 |= ins1; }
            else                 { frame0 = ins0; frame1 = ins1; }

            if (g == 0) {
                float d0, d1;
                asm("sqrt.approx.f32 %0, %1;" : "=f"(d0) : "f"(sq0));
                asm("sqrt.approx.f32 %0, %1;" : "=f"(d1) : "f"(sq1));
                out_dists[(size_t)box * N_POINTS]      = d0;
                out_dists[(size_t)box * N_POINTS + 16] = d1;
            }
        }
        town0 |= (frame0 && !anyw0);
        town1 |= (frame1 && !anyw1);
    }

    if (g == 0) {
        out[OUT_CONTAINS + (size_t)c * N_POINTS + n0]      = town0 ? 1.0f : 0.0f;
        out[OUT_CONTAINS + (size_t)c * N_POINTS + n0 + 16] = town1 ? 1.0f : 0.0f;
    }
}

extern "C" void kernel_launch(void* const* d_in, const int* in_sizes, int n_in,
                              void* d_out, int out_size) {
    const float* data  = (const float*)d_in[0];
    const float* shape = (const float*)d_in[1];
    float* out = (float*)d_out;

    dim3 grid(N_POINTS / 256, NUM_CLASSES);
    geom_kernel<<<grid, 256>>>(data, shape, out);
}

// round 14
// speedup vs baseline: 2.3717x; 1.5145x over previous
#include <cuda_runtime.h>
#include <cuda_fp16.h>

#define N_POINTS    32768
#define EMB         64
#define NUM_CLASSES 50
#define NUM_HOUSES  5
#define NUM_WIN     6            // NUM_WINDOWS + 1 (last = frame)
#define BOXES       (NUM_HOUSES * NUM_WIN)   // 30

// Output: data (N*64) | contains (50*N) | dists (50*30*N)
#define OUT_CONTAINS ((size_t)N_POINTS * EMB)
#define OUT_DISTS    (OUT_CONTAINS + (size_t)NUM_CLASSES * N_POINTS)

typedef unsigned int u32;

__device__ __forceinline__ u32 h2max(u32 a, u32 b) {
    u32 r; asm("max.f16x2 %0, %1, %2;" : "=r"(r) : "r"(a), "r"(b)); return r;
}
__device__ __forceinline__ u32 h2min(u32 a, u32 b) {
    u32 r; asm("min.f16x2 %0, %1, %2;" : "=r"(r) : "r"(a), "r"(b)); return r;
}
__device__ __forceinline__ u32 h2sub(u32 a, u32 b) {
    u32 r; asm("sub.rn.f16x2 %0, %1, %2;" : "=r"(r) : "r"(a), "r"(b)); return r;
}
__device__ __forceinline__ u32 h2add(u32 a, u32 b) {
    u32 r; asm("add.rn.f16x2 %0, %1, %2;" : "=r"(r) : "r"(a), "r"(b)); return r;
}
__device__ __forceinline__ u32 h2fma(u32 a, u32 b, u32 c) {
    u32 r; asm("fma.rn.f16x2 %0, %1, %2, %3;" : "=r"(r) : "r"(a), "r"(b), "r"(c)); return r;
}
__device__ __forceinline__ u32 h2mul(u32 a, u32 b) {
    u32 r; asm("mul.rn.f16x2 %0, %1, %2;" : "=r"(r) : "r"(a), "r"(b)); return r;
}
// pack two f32 -> f16x2 (lo in low half). cvt d, a, b: d.hi=a, d.lo=b.
__device__ __forceinline__ u32 packh2(float lo, float hi) {
    u32 r; asm("cvt.rn.f16x2.f32 %0, %1, %2;" : "=r"(r) : "f"(hi), "f"(lo)); return r;
}
__device__ __forceinline__ void h2tof32(u32 v, float& x, float& y) {
    asm("{\n\t.reg .b16 l, h;\n\tmov.b32 {l, h}, %2;\n\t"
        "cvt.f32.f16 %0, l;\n\tcvt.f32.f16 %1, h;\n\t}"
        : "=f"(x), "=f"(y) : "r"(v));
}

// One 2-dim fp16x2 step: clamp (HMNMX2 x2, alu) + sub + fma (fma pipe).
#define H2STEP_FMA(P, LO, HI, ACC) {                              \
    const u32 _d = h2sub((P), h2min(h2max((P), (LO)), (HI)));     \
    (ACC) = h2fma(_d, _d, (ACC)); }
#define H2STEP_MUL(P, LO, HI, ACC) {                              \
    const u32 _d = h2sub((P), h2min(h2max((P), (LO)), (HI)));     \
    (ACC) = h2mul(_d, _d); }

#define SLOT_STRIDE 9   // 8 data uint4 + 1 pad -> 144B group skew (4 banks)

__global__ __launch_bounds__(256, 3)
void geom_kernel(const float* __restrict__ data,
                 const float* __restrict__ shape,   // [50][5][6][2][64]
                 float* __restrict__ out)
{
    // s_box[box][g*9 + k] = uint4 (lo_h2, hi_h2, lo_h2, hi_h2) covering
    // dims g*32 + 4k .. +3 (two f16x2 pairs). Group stride 9 uint4 = 36
    // words == 4 banks (mod 32) -> the two half-warp broadcast addresses
    // hit disjoint bank quads: conflict-free LDS.128.
    __shared__ uint4 s_box[BOXES][2 * SLOT_STRIDE];

    const int c   = blockIdx.y;
    const int tid = threadIdx.x;

    // ---- stage this class's 30 boxes as fp16x2 lo/hi pairs ----
    const float* sb = shape + (size_t)c * (BOXES * 2 * EMB);
    #pragma unroll
    for (int e = tid; e < BOXES * 16; e += 256) {
        const int box = e >> 4;
        const int s   = e & 15;           // slot: 4 dims
        const int d   = (s >> 3) * 32 + (s & 7) * 4;
        const float4 a = *reinterpret_cast<const float4*>(sb + box * 128 + d);
        const float4 b = *reinterpret_cast<const float4*>(sb + box * 128 + 64 + d);
        const float lo0 = fminf(a.x, b.x), hi0 = fmaxf(a.x, b.x);
        const float lo1 = fminf(a.y, b.y), hi1 = fmaxf(a.y, b.y);
        const float lo2 = fminf(a.z, b.z), hi2 = fmaxf(a.z, b.z);
        const float lo3 = fminf(a.w, b.w), hi3 = fmaxf(a.w, b.w);
        uint4 v;
        v.x = packh2(lo0, lo1);  v.y = packh2(hi0, hi1);
        v.z = packh2(lo2, lo3);  v.w = packh2(hi2, hi3);
        s_box[box][(s >> 3) * SLOT_STRIDE + (s & 7)] = v;
    }

    // ---- data passthrough (class-slice 0 only): linear block copy ----
    if (blockIdx.y == 0) {
        // this block covers 256 points = 16384 floats = 4096 float4
        const float4* src = reinterpret_cast<const float4*>(
            data + (size_t)blockIdx.x * 256 * EMB);
        float4* dst = reinterpret_cast<float4*>(
            out + (size_t)blockIdx.x * 256 * EMB);
        #pragma unroll
        for (int k = 0; k < 16; k++)
            dst[tid + 256 * k] = src[tid + 256 * k];
    }
    __syncthreads();

    // ---- 2 threads per point, 2 points per thread: 32 points/warp ----
    const int lane = tid & 31;
    const int warp = tid >> 5;
    const int g    = lane >> 4;   // dim group: dims [g*32, g*32+32)
    const int i    = lane & 15;
    const int n0   = blockIdx.x * 256 + warp * 32 + i;   // and n0+16

    // 32 dims per point = 16 f16x2 pairs, two points
    u32 p0h[16], p1h[16];
    {
        const float4* dp0 = reinterpret_cast<const float4*>(
            data + (size_t)n0 * EMB + g * 32);
        const float4* dp1 = reinterpret_cast<const float4*>(
            data + (size_t)(n0 + 16) * EMB + g * 32);
        #pragma unroll
        for (int k = 0; k < 8; k++) {
            const float4 v0 = dp0[k];
            const float4 v1 = dp1[k];
            p0h[2 * k]     = packh2(v0.x, v0.y);
            p0h[2 * k + 1] = packh2(v0.z, v0.w);
            p1h[2 * k]     = packh2(v1.x, v1.y);
            p1h[2 * k + 1] = packh2(v1.z, v1.w);
        }
    }

    float* __restrict__ out_dists = out + OUT_DISTS
                                  + (size_t)c * BOXES * N_POINTS + n0;

    bool town0 = false, town1 = false;
    #pragma unroll 1
    for (int h = 0; h < NUM_HOUSES; h++) {
        bool anyw0 = false, frame0 = false;
        bool anyw1 = false, frame1 = false;
        #pragma unroll 2
        for (int w = 0; w < NUM_WIN; w++) {
            const int box = h * NUM_WIN + w;
            const uint4* bx = &s_box[box][g * SLOT_STRIDE];
            // 8 accumulator chains (4 per point), each 4 HFMA2 deep:
            // bounds fp16 rounding drift, maximizes ILP.
            u32 a0, a1, a2, a3, b0, b1, b2, b3;
            {
                const uint4 q = bx[0];
                H2STEP_MUL(p0h[0], q.x, q.y, a0)
                H2STEP_MUL(p0h[1], q.z, q.w, a1)
                H2STEP_MUL(p1h[0], q.x, q.y, b0)
                H2STEP_MUL(p1h[1], q.z, q.w, b1)
            }
            {
                const uint4 q = bx[1];
                H2STEP_MUL(p0h[2], q.x, q.y, a2)
                H2STEP_MUL(p0h[3], q.z, q.w, a3)
                H2STEP_MUL(p1h[2], q.x, q.y, b2)
                H2STEP_MUL(p1h[3], q.z, q.w, b3)
            }
            #pragma unroll
            for (int k = 2; k < 8; k += 2) {
                const uint4 q0 = bx[k];
                H2STEP_FMA(p0h[2 * k],     q0.x, q0.y, a0)
                H2STEP_FMA(p0h[2 * k + 1], q0.z, q0.w, a1)
                H2STEP_FMA(p1h[2 * k],     q0.x, q0.y, b0)
                H2STEP_FMA(p1h[2 * k + 1], q0.z, q0.w, b1)
                const uint4 q1 = bx[k + 1];
                H2STEP_FMA(p0h[2 * k + 2], q1.x, q1.y, a2)
                H2STEP_FMA(p0h[2 * k + 3], q1.z, q1.w, a3)
                H2STEP_FMA(p1h[2 * k + 2], q1.x, q1.y, b2)
                H2STEP_FMA(p1h[2 * k + 3], q1.z, q1.w, b3)
            }
            // combine chains (3 HADD2 per point), widen to fp32
            const u32 sa = h2add(h2add(a0, a1), h2add(a2, a3));
            const u32 sb2 = h2add(h2add(b0, b1), h2add(b2, b3));
            float x0, y0, x1, y1;
            h2tof32(sa, x0, y0);
            h2tof32(sb2, x1, y1);
            float sq0 = x0 + y0;
            float sq1 = x1 + y1;
            // combine the two 32-dim halves (lanes xor 16); 1 shfl per point
            sq0 += __shfl_xor_sync(0xffffffffu, sq0, 16);
            sq1 += __shfl_xor_sync(0xffffffffu, sq1, 16);

            // inside <=> all fp16 deltas 0 <=> sq == 0 (partials >= 0)
            const bool ins0 = (sq0 == 0.0f);
            const bool ins1 = (sq1 == 0.0f);
            if (w < NUM_WIN - 1) { anyw0 |= ins0; anyw1 |= ins1; }
            else                 { frame0 = ins0; frame1 = ins1; }

            if (g == 0) {
                float d0, d1;
                asm("sqrt.approx.f32 %0, %1;" : "=f"(d0) : "f"(sq0));
                asm("sqrt.approx.f32 %0, %1;" : "=f"(d1) : "f"(sq1));
                out_dists[(size_t)box * N_POINTS]      = d0;
                out_dists[(size_t)box * N_POINTS + 16] = d1;
            }
        }
        town0 |= (frame0 && !anyw0);
        town1 |= (frame1 && !anyw1);
    }

    if (g == 0) {
        out[OUT_CONTAINS + (size_t)c * N_POINTS + n0]      = town0 ? 1.0f : 0.0f;
        out[OUT_CONTAINS + (size_t)c * N_POINTS + n0 + 16] = town1 ? 1.0f : 0.0f;
    }
}

extern "C" void kernel_launch(void* const* d_in, const int* in_sizes, int n_in,
                              void* d_out, int out_size) {
    const float* data  = (const float*)d_in[0];
    const float* shape = (const float*)d_in[1];
    float* out = (float*)d_out;

    dim3 grid(N_POINTS / 256, NUM_CLASSES);
    geom_kernel<<<grid, 256>>>(data, shape, out);
}

// round 15
// speedup vs baseline: 2.5255x; 1.0648x over previous
#include <cuda_runtime.h>
#include <cuda_fp16.h>

#define N_POINTS    32768
#define EMB         64
#define NUM_CLASSES 50
#define NUM_HOUSES  5
#define NUM_WIN     6            // NUM_WINDOWS + 1 (last = frame)
#define BOXES       (NUM_HOUSES * NUM_WIN)   // 30

// Output: data (N*64) | contains (50*N) | dists (50*30*N)
#define OUT_CONTAINS ((size_t)N_POINTS * EMB)
#define OUT_DISTS    (OUT_CONTAINS + (size_t)NUM_CLASSES * N_POINTS)

typedef unsigned int u32;

__device__ __forceinline__ u32 h2max(u32 a, u32 b) {
    u32 r; asm("max.f16x2 %0, %1, %2;" : "=r"(r) : "r"(a), "r"(b)); return r;
}
__device__ __forceinline__ u32 h2min(u32 a, u32 b) {
    u32 r; asm("min.f16x2 %0, %1, %2;" : "=r"(r) : "r"(a), "r"(b)); return r;
}
__device__ __forceinline__ u32 h2sub(u32 a, u32 b) {
    u32 r; asm("sub.rn.f16x2 %0, %1, %2;" : "=r"(r) : "r"(a), "r"(b)); return r;
}
__device__ __forceinline__ u32 h2add(u32 a, u32 b) {
    u32 r; asm("add.rn.f16x2 %0, %1, %2;" : "=r"(r) : "r"(a), "r"(b)); return r;
}
__device__ __forceinline__ u32 h2fma(u32 a, u32 b, u32 c) {
    u32 r; asm("fma.rn.f16x2 %0, %1, %2, %3;" : "=r"(r) : "r"(a), "r"(b), "r"(c)); return r;
}
__device__ __forceinline__ u32 h2mul(u32 a, u32 b) {
    u32 r; asm("mul.rn.f16x2 %0, %1, %2;" : "=r"(r) : "r"(a), "r"(b)); return r;
}
// pack two f32 -> f16x2 (lo in low half). cvt d, a, b: d.hi=a, d.lo=b.
__device__ __forceinline__ u32 packh2(float lo, float hi) {
    u32 r; asm("cvt.rn.f16x2.f32 %0, %1, %2;" : "=r"(r) : "f"(hi), "f"(lo)); return r;
}
__device__ __forceinline__ void h2tof32(u32 v, float& x, float& y) {
    asm("{\n\t.reg .b16 l, h;\n\tmov.b32 {l, h}, %2;\n\t"
        "cvt.f32.f16 %0, l;\n\tcvt.f32.f16 %1, h;\n\t}"
        : "=f"(x), "=f"(y) : "r"(v));
}

// One 2-dim fp16x2 step: clamp (HMNMX2 x2, alu) + sub + fma (fma pipe).
#define H2STEP_FMA(P, LO, HI, ACC) {                              \
    const u32 _d = h2sub((P), h2min(h2max((P), (LO)), (HI)));     \
    (ACC) = h2fma(_d, _d, (ACC)); }
#define H2STEP_MUL(P, LO, HI, ACC) {                              \
    const u32 _d = h2sub((P), h2min(h2max((P), (LO)), (HI)));     \
    (ACC) = h2mul(_d, _d); }

#define SLOT_STRIDE 9   // 8 data uint4 + 1 pad -> 144B group skew (4 banks)

__global__ __launch_bounds__(256, 3)
void geom_kernel(const float* __restrict__ data,
                 const float* __restrict__ shape,   // [50][5][6][2][64]
                 float* __restrict__ out)
{
    __shared__ uint4 s_box[BOXES][2 * SLOT_STRIDE];

    const int c   = blockIdx.y;
    const int tid = threadIdx.x;

    // ---- stage this class's 30 boxes as fp16x2 lo/hi pairs ----
    const float* sb = shape + (size_t)c * (BOXES * 2 * EMB);
    #pragma unroll
    for (int e = tid; e < BOXES * 16; e += 256) {
        const int box = e >> 4;
        const int s   = e & 15;           // slot: 4 dims
        const int d   = (s >> 3) * 32 + (s & 7) * 4;
        const float4 a = *reinterpret_cast<const float4*>(sb + box * 128 + d);
        const float4 b = *reinterpret_cast<const float4*>(sb + box * 128 + 64 + d);
        uint4 v;
        v.x = packh2(fminf(a.x, b.x), fminf(a.y, b.y));
        v.y = packh2(fmaxf(a.x, b.x), fmaxf(a.y, b.y));
        v.z = packh2(fminf(a.z, b.z), fminf(a.w, b.w));
        v.w = packh2(fmaxf(a.z, b.z), fmaxf(a.w, b.w));
        s_box[box][(s >> 3) * SLOT_STRIDE + (s & 7)] = v;
    }

    // ---- data passthrough (class-slice 0 only): linear block copy ----
    if (blockIdx.y == 0) {
        const float4* src = reinterpret_cast<const float4*>(
            data + (size_t)blockIdx.x * 256 * EMB);
        float4* dst = reinterpret_cast<float4*>(
            out + (size_t)blockIdx.x * 256 * EMB);
        #pragma unroll
        for (int k = 0; k < 16; k++)
            dst[tid + 256 * k] = src[tid + 256 * k];
    }
    __syncthreads();

    // ---- 2 threads per point, 2 points per thread: 32 points/warp ----
    const int lane = tid & 31;
    const int warp = tid >> 5;
    const int g    = lane >> 4;   // dim group: dims [g*32, g*32+32)
    const int i    = lane & 15;
    const int n0   = blockIdx.x * 256 + warp * 32 + i;   // and n0+16

    // 32 dims per point = 16 f16x2 pairs, two points
    u32 p0h[16], p1h[16];
    {
        const float4* dp0 = reinterpret_cast<const float4*>(
            data + (size_t)n0 * EMB + g * 32);
        const float4* dp1 = reinterpret_cast<const float4*>(
            data + (size_t)(n0 + 16) * EMB + g * 32);
        #pragma unroll
        for (int k = 0; k < 8; k++) {
            const float4 v0 = dp0[k];
            const float4 v1 = dp1[k];
            p0h[2 * k]     = packh2(v0.x, v0.y);
            p0h[2 * k + 1] = packh2(v0.z, v0.w);
            p1h[2 * k]     = packh2(v1.x, v1.y);
            p1h[2 * k + 1] = packh2(v1.z, v1.w);
        }
    }

    // dual-store: g==0 lanes own point n0, g==1 lanes own point n0+16.
    // After the xor-16 shuffle both halves hold both sums, so each half
    // stores its own point: no predicated-off sqrt/store slots.
    float* __restrict__ out_dists = out + OUT_DISTS
                                  + (size_t)c * BOXES * N_POINTS + n0
                                  + g * 16;

    bool town0 = false, town1 = false;
    #pragma unroll 1
    for (int h = 0; h < NUM_HOUSES; h++) {
        bool anyw0 = false, frame0 = false;
        bool anyw1 = false, frame1 = false;
        #pragma unroll 3
        for (int w = 0; w < NUM_WIN; w++) {
            const int box = h * NUM_WIN + w;
            const uint4* bx = &s_box[box][g * SLOT_STRIDE];
            // 8 accumulator chains (4 per point), each 4 HFMA2 deep
            u32 a0, a1, a2, a3, b0, b1, b2, b3;
            {
                const uint4 q = bx[0];
                H2STEP_MUL(p0h[0], q.x, q.y, a0)
                H2STEP_MUL(p0h[1], q.z, q.w, a1)
                H2STEP_MUL(p1h[0], q.x, q.y, b0)
                H2STEP_MUL(p1h[1], q.z, q.w, b1)
            }
            {
                const uint4 q = bx[1];
                H2STEP_MUL(p0h[2], q.x, q.y, a2)
                H2STEP_MUL(p0h[3], q.z, q.w, a3)
                H2STEP_MUL(p1h[2], q.x, q.y, b2)
                H2STEP_MUL(p1h[3], q.z, q.w, b3)
            }
            #pragma unroll
            for (int k = 2; k < 8; k += 2) {
                const uint4 q0 = bx[k];
                H2STEP_FMA(p0h[2 * k],     q0.x, q0.y, a0)
                H2STEP_FMA(p0h[2 * k + 1], q0.z, q0.w, a1)
                H2STEP_FMA(p1h[2 * k],     q0.x, q0.y, b0)
                H2STEP_FMA(p1h[2 * k + 1], q0.z, q0.w, b1)
                const uint4 q1 = bx[k + 1];
                H2STEP_FMA(p0h[2 * k + 2], q1.x, q1.y, a2)
                H2STEP_FMA(p0h[2 * k + 3], q1.z, q1.w, a3)
                H2STEP_FMA(p1h[2 * k + 2], q1.x, q1.y, b2)
                H2STEP_FMA(p1h[2 * k + 3], q1.z, q1.w, b3)
            }
            // combine chains, widen to fp32
            const u32 sa  = h2add(h2add(a0, a1), h2add(a2, a3));
            const u32 sb2 = h2add(h2add(b0, b1), h2add(b2, b3));
            float x0, y0, x1, y1;
            h2tof32(sa, x0, y0);
            h2tof32(sb2, x1, y1);
            float sq0 = x0 + y0;
            float sq1 = x1 + y1;
            // combine the two 32-dim halves (lanes xor 16)
            sq0 += __shfl_xor_sync(0xffffffffu, sq0, 16);
            sq1 += __shfl_xor_sync(0xffffffffu, sq1, 16);

            // inside <=> all fp16 deltas 0 <=> sq == 0 (partials >= 0)
            const bool ins0 = (sq0 == 0.0f);
            const bool ins1 = (sq1 == 0.0f);
            if (w < NUM_WIN - 1) { anyw0 |= ins0; anyw1 |= ins1; }
            else                 { frame0 = ins0; frame1 = ins1; }

            // each half-warp stores its own point: g==0 -> sq0, g==1 -> sq1
            const float sqm = g ? sq1 : sq0;
            float dm;
            asm("sqrt.approx.f32 %0, %1;" : "=f"(dm) : "f"(sqm));
            out_dists[(size_t)box * N_POINTS] = dm;
        }
        town0 |= (frame0 && !anyw0);
        town1 |= (frame1 && !anyw1);
    }

    // contains: g==0 stores point0, g==1 stores point1
    const bool townm = g ? town1 : town0;
    out[OUT_CONTAINS + (size_t)c * N_POINTS + n0 + g * 16] = townm ? 1.0f : 0.0f;
}

extern "C" void kernel_launch(void* const* d_in, const int* in_sizes, int n_in,
                              void* d_out, int out_size) {
    const float* data  = (const float*)d_in[0];
    const float* shape = (const float*)d_in[1];
    float* out = (float*)d_out;

    dim3 grid(N_POINTS / 256, NUM_CLASSES);
    geom_kernel<<<grid, 256>>>(data, shape, out);
}